// round 6
// baseline (speedup 1.0000x reference)
#include <cuda_runtime.h>
#include <cuda_bf16.h>
#include <math.h>

// BRITS-style recurrent imputation. B=256, T=512, F=64, H=128, gates=512.
// Flat 64 persistent CTAs x 256 threads; CTA owns 4 batch rows for the whole
// scan. Small weights live in smem; gate weights stream k-major from L2 with
// deep unroll (MLP 16). Inputs for t+1 prefetched under the long compute phase.
// Output: [loss(1), predictions(256), imputations(256*512*64)].

#define Bsz 256
#define Tt  512
#define Ff  64
#define Hh  128
#define ROWS 4
#define NCTA 64

// ---------------- device-global staging (static, allocation-free) ----------
__device__ __align__(16) float g_W[256 * 512];      // gates weights k-major [k][out]
__device__ float g_bg[512];                         // b_ih + b_hh
__device__ float g_WdhT[Ff * Hh];                   // [k][hu]
__device__ float g_WhrT[Hh * Ff];                   // [k][f]
__device__ float g_WfrT[Ff * Ff];                   // [k][f], diag zeroed
__device__ float g_WwcT[2 * Ff * Ff];               // [k][f]
__device__ float g_wdx[Ff];
__device__ float g_inv_msum[Tt];
__device__ float g_istrain;
__device__ float g_xloss;
__device__ float g_yloss;

// ---------------- helpers --------------------------------------------------
__device__ __forceinline__ unsigned long long splat2(float w) {
    unsigned long long r; unsigned int wi = __float_as_uint(w);
    asm("mov.b64 %0, {%1, %2};" : "=l"(r) : "r"(wi), "r"(wi));
    return r;
}
__device__ __forceinline__ unsigned long long fma2(unsigned long long a,
                                                   unsigned long long b,
                                                   unsigned long long c) {
    unsigned long long d;
    asm("fma.rn.f32x2 %0, %1, %2, %3;" : "=l"(d) : "l"(a), "l"(b), "l"(c));
    return d;
}
union F2U { unsigned long long u; float2 f; };

__device__ __forceinline__ float sigm(float x) { return 1.f / (1.f + __expf(-x)); }
__device__ __forceinline__ float tanh_e(float x) { return 1.f - 2.f / (__expf(2.f * x) + 1.f); }

// ---------------- prep: transposes + msum + zero accumulators -------------
__global__ void prep_all(const float* __restrict__ masks, const float* __restrict__ is_train,
                         const float* __restrict__ W_dh, const float* __restrict__ W_dx,
                         const float* __restrict__ W_hr, const float* __restrict__ W_fr,
                         const float* __restrict__ W_wc,
                         const float* __restrict__ W_ih, const float* __restrict__ b_ih,
                         const float* __restrict__ W_hh, const float* __restrict__ b_hh) {
    __shared__ float red[256];
    const int bx = blockIdx.x;
    if (bx < Tt) {                       // msum(t)
        float s = 0.f;
        for (int i = threadIdx.x; i < Bsz * Ff; i += 256) {
            int b = i / Ff, f = i % Ff;
            s += masks[(b * Tt + bx) * Ff + f];
        }
        red[threadIdx.x] = s; __syncthreads();
        for (int off = 128; off > 0; off >>= 1) {
            if (threadIdx.x < off) red[threadIdx.x] += red[threadIdx.x + off];
            __syncthreads();
        }
        if (threadIdx.x == 0) g_inv_msum[bx] = 1.f / (red[0] + 1e-5f);
        return;
    }
    if (bx == Tt) {                      // is_train sum + zero losses
        red[threadIdx.x] = is_train[threadIdx.x]; __syncthreads();
        for (int off = 128; off > 0; off >>= 1) {
            if (threadIdx.x < off) red[threadIdx.x] += red[threadIdx.x + off];
            __syncthreads();
        }
        if (threadIdx.x == 0) { g_istrain = red[0]; g_xloss = 0.f; g_yloss = 0.f; }
        return;
    }
    // transposes, grid-stride over the remaining blocks
    const int idx = (bx - Tt - 1) * 256 + threadIdx.x;
    const int stride = 128 * 256;
    for (int i = idx; i < 256 * 512; i += stride) {
        int k = i >> 9, o = i & 511;
        g_W[i] = (k < 128) ? W_ih[o * 128 + k] : W_hh[o * 128 + (k - 128)];
    }
    for (int i = idx; i < 512; i += stride) g_bg[i] = b_ih[i] + b_hh[i];
    for (int i = idx; i < Ff * Hh; i += stride) { int k = i / Hh, o = i % Hh; g_WdhT[i] = W_dh[o * Ff + k]; }
    for (int i = idx; i < Hh * Ff; i += stride) { int k = i / Ff, o = i % Ff; g_WhrT[i] = W_hr[o * Hh + k]; }
    for (int i = idx; i < Ff * Ff; i += stride) { int k = i / Ff, o = i % Ff; g_WfrT[i] = (o == k) ? 0.f : W_fr[o * Ff + k]; }
    for (int i = idx; i < 2 * Ff * Ff; i += stride) { int k = i / Ff, o = i % Ff; g_WwcT[i] = W_wc[o * (2 * Ff) + k]; }
    for (int i = idx; i < Ff; i += stride) g_wdx[i] = W_dx[i * Ff + i];
}

// ---------------- smem layout for main kernel ------------------------------
struct __align__(16) SmemMain {
    float WdhT[Ff * Hh];        // 32KB
    float WhrT[Hh * Ff];        // 32KB
    float WfrT[Ff * Ff];        // 16KB
    float WwcT[2 * Ff * Ff];    // 32KB
    float actT[256 * 4];        // [k][r]: 0-63 c_c, 64-127 m, 128-255 h(decayed)
    float hT[Hh * 4];           // raw h [hu*4+r]
    float cT[Hh * 4];           // cell state
    float dT[Ff * 4];
    float gxT[Ff * 4];
    float xcT[Ff * 4];
    float gT[512 * 4];          // gates preact [out][r]  (8KB)
    float inv_msum[Tt];
    float bg[512];
    float b_dh[Hh];
    float b_dx[Ff]; float b_hr[Ff]; float b_fr[Ff]; float b_wc[Ff];
    float wdx[Ff];
    float red[256];
};

// ---------------- main persistent scan kernel ------------------------------
__global__ __launch_bounds__(256, 1)
void brits_main(const float* __restrict__ values, const float* __restrict__ masks,
                const float* __restrict__ deltas, const float* __restrict__ labels,
                const float* __restrict__ is_train,
                const float* __restrict__ b_dh, const float* __restrict__ b_dx,
                const float* __restrict__ b_hr, const float* __restrict__ b_fr,
                const float* __restrict__ b_wc,
                const float* __restrict__ W_out, const float* __restrict__ b_out,
                float* __restrict__ out) {
    extern __shared__ char smem_raw[];
    SmemMain* s = reinterpret_cast<SmemMain*>(smem_raw);

    const int tid = threadIdx.x;
    const int b0 = blockIdx.x * ROWS;
    const int fr_f = tid & 63;             // F-elementwise mapping
    const int fr_r = tid >> 6;
    const int hu = tid & 127;              // H mapping
    const int hp = tid >> 7;               // row-pair 0/1

    // ---- init: stage weights into smem ----
    for (int i = tid; i < Ff * Hh; i += 256) s->WdhT[i] = g_WdhT[i];
    for (int i = tid; i < Hh * Ff; i += 256) s->WhrT[i] = g_WhrT[i];
    for (int i = tid; i < Ff * Ff; i += 256) s->WfrT[i] = g_WfrT[i];
    for (int i = tid; i < 2 * Ff * Ff; i += 256) s->WwcT[i] = g_WwcT[i];
    for (int i = tid; i < Tt; i += 256) s->inv_msum[i] = g_inv_msum[i];
    for (int i = tid; i < 512; i += 256) s->bg[i] = g_bg[i];
    if (tid < Hh) s->b_dh[tid] = b_dh[tid];
    if (tid < Ff) {
        s->b_dx[tid] = b_dx[tid]; s->b_hr[tid] = b_hr[tid];
        s->b_fr[tid] = b_fr[tid]; s->b_wc[tid] = b_wc[tid];
        s->wdx[tid] = g_wdx[tid];
    }
    s->hT[hu * 4 + 2 * hp] = 0.f; s->hT[hu * 4 + 2 * hp + 1] = 0.f;
    s->cT[hu * 4 + 2 * hp] = 0.f; s->cT[hu * 4 + 2 * hp + 1] = 0.f;
    float lacc = 0.f;
    __syncthreads();

    const float2* wp2 = reinterpret_cast<const float2*>(g_W) + tid;  // [k][out pair tid]
    int gidx = ((b0 + fr_r) * Tt) * Ff + fr_f;

    // prefetch t = 0
    float xv = values[gidx], mv = masks[gidx], dv = deltas[gidx];

    for (int t = 0; t < Tt; ++t) {
        // ---- Stage A: publish x,m,d; gamma_x -----------------------------
        s->actT[(64 + fr_f) * 4 + fr_r] = mv;
        s->dT[fr_f * 4 + fr_r] = dv;
        s->gxT[fr_f * 4 + fr_r] = __expf(-fmaxf(dv * s->wdx[fr_f] + s->b_dx[fr_f], 0.f));
        __syncthreads();

        // ---- Stage B: gamma_h + decay h ----------------------------------
        {
            float a0 = 0.f, a1 = 0.f;
#pragma unroll 8
            for (int k = 0; k < Ff; ++k) {
                const float w = s->WdhT[k * Hh + hu];
                const float2 dp = *reinterpret_cast<const float2*>(&s->dT[k * 4 + 2 * hp]);
                a0 += w * dp.x;
                a1 += w * dp.y;
            }
            const float bb = s->b_dh[hu];
            const float g0 = __expf(-fmaxf(a0 + bb, 0.f));
            const float g1 = __expf(-fmaxf(a1 + bb, 0.f));
            s->actT[(128 + hu) * 4 + 2 * hp]     = s->hT[hu * 4 + 2 * hp] * g0;
            s->actT[(128 + hu) * 4 + 2 * hp + 1] = s->hT[hu * 4 + 2 * hp + 1] * g1;
        }
        // prefetch t+1 inputs (latency hidden under E1/C/D)
        const int ng = (t + 1 < Tt) ? gidx + Ff : gidx;
        const float xn = values[ng];
        const float mn = masks[ng];
        const float dn = deltas[ng];
        __syncthreads();

        // ---- Stage E1: gates GEMM, k=64..255 (m + decayed h) -------------
        unsigned long long acc00 = 0ull, acc01 = 0ull, acc10 = 0ull, acc11 = 0ull;
        {
#pragma unroll 16
            for (int k = 64; k < 256; ++k) {
                const float2 wv = wp2[k * 256];
                const ulonglong2 av = *reinterpret_cast<const ulonglong2*>(&s->actT[k * 4]);
                const unsigned long long w0 = splat2(wv.x);
                const unsigned long long w1 = splat2(wv.y);
                acc00 = fma2(w0, av.x, acc00);
                acc01 = fma2(w0, av.y, acc01);
                acc10 = fma2(w1, av.x, acc10);
                acc11 = fma2(w1, av.y, acc11);
            }
        }
        // ---- Stage C (same phase): x_h -----------------------------------
        float x_h;
        {
            float acc = 0.f;
#pragma unroll 8
            for (int k = 0; k < Hh; ++k)
                acc += s->WhrT[k * Ff + fr_f] * s->actT[(128 + k) * 4 + fr_r];
            x_h = acc + s->b_hr[fr_f];
        }
        const float l1 = fabsf(xv - x_h) * mv;
        const float x_c = mv * xv + (1.f - mv) * x_h;
        s->xcT[fr_f * 4 + fr_r] = x_c;
        __syncthreads();

        // ---- Stage D: z_h, alpha, c_h, c_c, losses -----------------------
        {
            float za = 0.f;
#pragma unroll 8
            for (int k = 0; k < Ff; ++k)
                za += s->WfrT[k * Ff + fr_f] * s->xcT[k * 4 + fr_r];
            const float z_h = za + s->b_fr[fr_f];
            float aa = 0.f;
#pragma unroll 8
            for (int k = 0; k < Ff; ++k)
                aa += s->WwcT[k * Ff + fr_f] * s->gxT[k * 4 + fr_r];
#pragma unroll 8
            for (int k = 0; k < Ff; ++k)
                aa += s->WwcT[(64 + k) * Ff + fr_f] * s->actT[(64 + k) * 4 + fr_r];
            const float alpha = aa + s->b_wc[fr_f];
            const float c_h = alpha * z_h + (1.f - alpha) * x_h;
            const float l2 = fabsf(xv - z_h) * mv;
            const float l3 = fabsf(xv - c_h) * mv;
            lacc += (l1 + l2 + l3) * s->inv_msum[t];
            const float c_c = mv * xv + (1.f - mv) * c_h;
            out[1 + Bsz + gidx] = c_c;                 // imputations [B,T,F]
            s->actT[fr_f * 4 + fr_r] = c_c;
        }
        __syncthreads();

        // ---- Stage E2: gates GEMM, k=0..63 (c_c); write gT ---------------
        {
#pragma unroll 16
            for (int k = 0; k < 64; ++k) {
                const float2 wv = wp2[k * 256];
                const ulonglong2 av = *reinterpret_cast<const ulonglong2*>(&s->actT[k * 4]);
                const unsigned long long w0 = splat2(wv.x);
                const unsigned long long w1 = splat2(wv.y);
                acc00 = fma2(w0, av.x, acc00);
                acc01 = fma2(w0, av.y, acc01);
                acc10 = fma2(w1, av.x, acc10);
                acc11 = fma2(w1, av.y, acc11);
            }
            F2U u00, u01, u10, u11;
            u00.u = acc00; u01.u = acc01; u10.u = acc10; u11.u = acc11;
            const int o0 = 2 * tid;
            const float bg0 = s->bg[o0], bg1 = s->bg[o0 + 1];
            *reinterpret_cast<float4*>(&s->gT[o0 * 4]) =
                make_float4(u00.f.x + bg0, u00.f.y + bg0, u01.f.x + bg0, u01.f.y + bg0);
            *reinterpret_cast<float4*>(&s->gT[(o0 + 1) * 4]) =
                make_float4(u10.f.x + bg1, u10.f.y + bg1, u11.f.x + bg1, u11.f.y + bg1);
        }
        __syncthreads();

        // ---- Stage F: LSTM update ----------------------------------------
#pragma unroll
        for (int s2 = 0; s2 < 2; ++s2) {
            const int r = 2 * hp + s2;
            const float ig = s->gT[hu * 4 + r];
            const float fg = s->gT[(128 + hu) * 4 + r];
            const float gg = s->gT[(256 + hu) * 4 + r];
            const float og = s->gT[(384 + hu) * 4 + r];
            const float cn = sigm(fg) * s->cT[hu * 4 + r] + sigm(ig) * tanh_e(gg);
            s->cT[hu * 4 + r] = cn;
            s->hT[hu * 4 + r] = sigm(og) * tanh_e(cn);
        }
        __syncthreads();

        // rotate prefetch
        xv = xn; mv = mn; dv = dn; gidx += Ff;
    }

    // ---- epilogue: x_loss block reduce ------------------------------------
    s->red[tid] = lacc; __syncthreads();
    for (int off = 128; off > 0; off >>= 1) {
        if (tid < off) s->red[tid] += s->red[tid + off];
        __syncthreads();
    }
    if (tid == 0) atomicAdd(&g_xloss, s->red[0]);

    // ---- epilogue: y head (warp w handles row w) --------------------------
    const int wid = tid >> 5, lid = tid & 31;
    if (wid < ROWS) {
        float acc = 0.f;
#pragma unroll
        for (int u = lid; u < Hh; u += 32)
            acc += s->hT[u * 4 + wid] * W_out[u];
#pragma unroll
        for (int off = 16; off > 0; off >>= 1)
            acc += __shfl_down_sync(0xffffffffu, acc, off);
        if (lid == 0) {
            const int b = b0 + wid;
            const float yh = acc + b_out[0];
            out[1 + b] = 1.f / (1.f + expf(-yh));
            const float lab = labels[b];
            const float mx = fmaxf(-yh, 0.f);
            const float yl = yh - yh * lab + mx + logf(expf(-mx) + expf(-yh - mx));
            atomicAdd(&g_yloss, yl * is_train[b]);
        }
    }
}

// ---------------- finalize --------------------------------------------------
__global__ void finalize_loss(float* __restrict__ out) {
    out[0] = g_xloss * (1.f / (float)Tt) + 0.3f * (g_yloss / (g_istrain + 1e-5f));
}

// ---------------- launch ----------------------------------------------------
extern "C" void kernel_launch(void* const* d_in, const int* in_sizes, int n_in,
                              void* d_out, int out_size) {
    (void)in_sizes; (void)n_in; (void)out_size;
    const float* values   = (const float*)d_in[0];
    const float* masks    = (const float*)d_in[1];
    const float* deltas   = (const float*)d_in[2];
    const float* labels   = (const float*)d_in[3];
    const float* is_train = (const float*)d_in[4];
    const float* W_dh = (const float*)d_in[5];
    const float* b_dh = (const float*)d_in[6];
    const float* W_dx = (const float*)d_in[7];
    const float* b_dx = (const float*)d_in[8];
    const float* W_hr = (const float*)d_in[9];
    const float* b_hr = (const float*)d_in[10];
    const float* W_fr = (const float*)d_in[11];
    const float* b_fr = (const float*)d_in[12];
    const float* W_wc = (const float*)d_in[13];
    const float* b_wc = (const float*)d_in[14];
    const float* W_ih = (const float*)d_in[15];
    const float* b_ih = (const float*)d_in[16];
    const float* W_hh = (const float*)d_in[17];
    const float* b_hh = (const float*)d_in[18];
    const float* W_out = (const float*)d_in[19];
    const float* b_out = (const float*)d_in[20];
    float* out = (float*)d_out;

    static const size_t smem_bytes = sizeof(SmemMain);
    cudaFuncSetAttribute(brits_main, cudaFuncAttributeMaxDynamicSharedMemorySize,
                         (int)smem_bytes);

    prep_all<<<Tt + 1 + 128, 256>>>(masks, is_train, W_dh, W_dx, W_hr, W_fr, W_wc,
                                    W_ih, b_ih, W_hh, b_hh);
    brits_main<<<NCTA, 256, smem_bytes>>>(values, masks, deltas, labels, is_train,
                                          b_dh, b_dx, b_hr, b_fr, b_wc, W_out, b_out, out);
    finalize_loss<<<1, 1>>>(out);
}

// round 7
// speedup vs baseline: 2.0323x; 2.0323x over previous
#include <cuda_runtime.h>
#include <cuda_bf16.h>
#include <math.h>

// BRITS-style recurrent imputation. B=256, T=512, F=64, H=128, gates=512.
// 32 clusters x 4 CTAs = 128 CTAs. Cluster owns 8 batch rows. CTA rank c owns:
//   - gate outputs for h-units [32c,32c+32) (all 4 gates): 128 outs, fp32
//     weights RESIDENT IN SMEM (128KB) -> stage E is pure LDS, no L2.
//   - f-slice [16c,16c+16) of the C (x_h) and D (z_h/alpha) matvecs (smem slices).
// B (gamma_h decay) duplicated per CTA (WdhT full in smem).
// Per step: 3 cluster syncs; DSMEM pushes of x_c, c_c, h slices.
// Output: [loss(1), predictions(256), imputations(256*512*64)].

#define Bsz 256
#define Tt  512
#define Ff  64
#define Hh  128
#define CROWS 8          // rows per cluster
#define NCLUST 32
#define NCTA (NCLUST * 4)

// ---------------- device-global staging (static, allocation-free) ----------
__device__ __align__(16) float g_Wg[4 * 256 * 128];   // [rank][k][lo]
__device__ float g_bgsl[4 * 128];                     // gate bias slice
__device__ float g_WdhT[64 * 128];                    // [k][hu]
__device__ float g_Whrsl[4 * 128 * 16];               // [rank][k][lf]
__device__ float g_Wfrsl[4 * 64 * 16];                // [rank][k][lf], diag zeroed
__device__ float g_Wwcsl[4 * 128 * 16];               // [rank][k][lf]
__device__ float g_wdx[64];
__device__ float g_inv_msum[Tt];
__device__ float g_istrain;
__device__ float g_xloss;
__device__ float g_yloss;

// ---------------- helpers --------------------------------------------------
__device__ __forceinline__ unsigned long long splat2(float w) {
    unsigned long long r; unsigned int wi = __float_as_uint(w);
    asm("mov.b64 %0, {%1, %2};" : "=l"(r) : "r"(wi), "r"(wi));
    return r;
}
__device__ __forceinline__ unsigned long long fma2(unsigned long long a,
                                                   unsigned long long b,
                                                   unsigned long long c) {
    unsigned long long d;
    asm("fma.rn.f32x2 %0, %1, %2, %3;" : "=l"(d) : "l"(a), "l"(b), "l"(c));
    return d;
}
union F2U { unsigned long long u; float2 f; };

__device__ __forceinline__ float sigm(float x) { return 1.f / (1.f + __expf(-x)); }
__device__ __forceinline__ float tanh_e(float x) { return 1.f - 2.f / (__expf(2.f * x) + 1.f); }

__device__ __forceinline__ void st_peer_f32(const void* smem_ptr, unsigned int peer, float v) {
    unsigned int la = (unsigned int)__cvta_generic_to_shared(smem_ptr);
    unsigned int ra;
    asm volatile("mapa.shared::cluster.u32 %0, %1, %2;" : "=r"(ra) : "r"(la), "r"(peer));
    asm volatile("st.shared::cluster.f32 [%0], %1;" :: "r"(ra), "f"(v));
}
__device__ __forceinline__ void push3(const void* p, unsigned int rank, float v) {
#pragma unroll
    for (int d = 1; d < 4; ++d) st_peer_f32(p, (rank + d) & 3u, v);
}
#define CSYNC() do { \
    asm volatile("barrier.cluster.arrive.aligned;" ::: "memory"); \
    asm volatile("barrier.cluster.wait.aligned;" ::: "memory"); } while (0)

// ---------------- prep -----------------------------------------------------
__global__ void prep_all(const float* __restrict__ masks, const float* __restrict__ is_train,
                         const float* __restrict__ W_dh, const float* __restrict__ W_dx,
                         const float* __restrict__ W_hr, const float* __restrict__ W_fr,
                         const float* __restrict__ W_wc,
                         const float* __restrict__ W_ih, const float* __restrict__ b_ih,
                         const float* __restrict__ W_hh, const float* __restrict__ b_hh) {
    __shared__ float red[256];
    const int bx = blockIdx.x;
    if (bx < Tt) {
        float s = 0.f;
        for (int i = threadIdx.x; i < Bsz * Ff; i += 256) {
            int b = i / Ff, f = i % Ff;
            s += masks[(b * Tt + bx) * Ff + f];
        }
        red[threadIdx.x] = s; __syncthreads();
        for (int off = 128; off > 0; off >>= 1) {
            if (threadIdx.x < off) red[threadIdx.x] += red[threadIdx.x + off];
            __syncthreads();
        }
        if (threadIdx.x == 0) g_inv_msum[bx] = 1.f / (red[0] + 1e-5f);
        return;
    }
    if (bx == Tt) {
        red[threadIdx.x] = is_train[threadIdx.x]; __syncthreads();
        for (int off = 128; off > 0; off >>= 1) {
            if (threadIdx.x < off) red[threadIdx.x] += red[threadIdx.x + off];
            __syncthreads();
        }
        if (threadIdx.x == 0) { g_istrain = red[0]; g_xloss = 0.f; g_yloss = 0.f; }
        return;
    }
    const int idx = (bx - Tt - 1) * 256 + threadIdx.x;
    const int stride = 128 * 256;
    // gate weight slices: [c][k][lo], lo = gate*32+ul, global out = gate*128 + 32c + ul
    for (int i = idx; i < 4 * 256 * 128; i += stride) {
        int c = i >> 15, k = (i >> 7) & 255, lo = i & 127;
        int gate = lo >> 5, ul = lo & 31;
        int go = gate * 128 + c * 32 + ul;
        g_Wg[i] = (k < 128) ? W_ih[go * 128 + k] : W_hh[go * 128 + (k - 128)];
    }
    for (int i = idx; i < 4 * 128; i += stride) {
        int c = i >> 7, lo = i & 127;
        int gate = lo >> 5, ul = lo & 31;
        int go = gate * 128 + c * 32 + ul;
        g_bgsl[i] = b_ih[go] + b_hh[go];
    }
    for (int i = idx; i < 64 * 128; i += stride) { int k = i >> 7, hu = i & 127; g_WdhT[i] = W_dh[hu * 64 + k]; }
    for (int i = idx; i < 4 * 128 * 16; i += stride) {
        int c = i >> 11, k = (i >> 4) & 127, lf = i & 15;
        g_Whrsl[i] = W_hr[(16 * c + lf) * 128 + k];
    }
    for (int i = idx; i < 4 * 64 * 16; i += stride) {
        int c = i >> 10, k = (i >> 4) & 63, lf = i & 15;
        int fg = 16 * c + lf;
        g_Wfrsl[i] = (k == fg) ? 0.f : W_fr[fg * 64 + k];
    }
    for (int i = idx; i < 4 * 128 * 16; i += stride) {
        int c = i >> 11, k = (i >> 4) & 127, lf = i & 15;
        g_Wwcsl[i] = W_wc[(16 * c + lf) * 128 + k];
    }
    for (int i = idx; i < 64; i += stride) g_wdx[i] = W_dx[i * 64 + i];
}

// ---------------- smem layout ----------------------------------------------
struct __align__(16) SmemMain {
    float Wg[256 * 128];      // 128KB gate weight slice [k][lo]
    float WdhT[64 * 128];     // 32KB  [k][hu]
    float Whrsl[128 * 16];    // 8KB   [k][lf]
    float Wfrsl[64 * 16];     // 4KB
    float Wwcsl[128 * 16];    // 8KB
    float actT[256 * 8];      // [k][row]: 0-63 c_c, 64-127 m, 128-255 decayed h
    float hT[128 * 8];        // raw h (full, replicated via DSMEM)
    float cT[32 * 8];         // my 32 units' cell state
    float dT[64 * 8];
    float gxT[64 * 8];
    float xcT[64 * 8];        // full x_c (exchange dest)
    float xT[64 * 8];
    float gTa[8 * 128];       // gate preact partial k<128  [row][lo]
    float gTb[8 * 128];       // partial k>=128
    float inv_msum[Tt];
    float bg[128];
    float b_dhv[128];
    float b_hrv[16]; float b_frv[16]; float b_wcv[16];
    float wdxv[64]; float b_dxv[64];
    float red[256];
};

// ---------------- main persistent scan kernel ------------------------------
__global__ __launch_bounds__(256, 1) __cluster_dims__(4, 1, 1)
void brits_main(const float* __restrict__ values, const float* __restrict__ masks,
                const float* __restrict__ deltas, const float* __restrict__ labels,
                const float* __restrict__ is_train,
                const float* __restrict__ b_dh, const float* __restrict__ b_dx,
                const float* __restrict__ b_hr, const float* __restrict__ b_fr,
                const float* __restrict__ b_wc,
                const float* __restrict__ W_out, const float* __restrict__ b_out,
                float* __restrict__ out) {
    extern __shared__ char smem_raw[];
    SmemMain* s = reinterpret_cast<SmemMain*>(smem_raw);

    unsigned int rank;
    asm("mov.u32 %0, %%cluster_ctarank;" : "=r"(rank));

    const int tid = threadIdx.x;
    const int b0 = (blockIdx.x >> 2) * CROWS;

    // ---- init smem ----
    for (int i = tid; i < 256 * 128; i += 256) s->Wg[i] = g_Wg[(rank << 15) + i];
    for (int i = tid; i < 64 * 128; i += 256) s->WdhT[i] = g_WdhT[i];
    for (int i = tid; i < 128 * 16; i += 256) s->Whrsl[i] = g_Whrsl[(rank << 11) + i];
    for (int i = tid; i < 64 * 16; i += 256) s->Wfrsl[i] = g_Wfrsl[(rank << 10) + i];
    for (int i = tid; i < 128 * 16; i += 256) s->Wwcsl[i] = g_Wwcsl[(rank << 11) + i];
    for (int i = tid; i < Tt; i += 256) s->inv_msum[i] = g_inv_msum[i];
    for (int i = tid; i < 128 * 8; i += 256) s->hT[i] = 0.f;
    if (tid < 128) { s->bg[tid] = g_bgsl[(rank << 7) + tid]; s->b_dhv[tid] = b_dh[tid]; }
    if (tid < 16) {
        s->b_hrv[tid] = b_hr[16 * rank + tid];
        s->b_frv[tid] = b_fr[16 * rank + tid];
        s->b_wcv[tid] = b_wc[16 * rank + tid];
    }
    if (tid < 64) { s->wdxv[tid] = g_wdx[tid]; s->b_dxv[tid] = b_dx[tid]; }
    if (tid < 32 * 8) s->cT[tid] = 0.f;
    float lacc = 0.f;
    __syncthreads();
    CSYNC();

    const int hu = tid & 127, hg = tid >> 7;          // B mapping
    const int lf = tid & 15, cr = (tid >> 4) & 7;     // C/D mapping (tid<128)
    const int fg = 16 * (int)rank + lf;
    const int ko = tid >> 7;                          // E k-half
    const int lo = tid & 127;                         // E output
    const int ful = tid & 31, frow = tid >> 5;        // F mapping

    for (int t = 0; t < Tt; ++t) {
        // ---- Stage A: inputs + gamma_x (duplicated) ----------------------
#pragma unroll
        for (int it = 0; it < 2; ++it) {
            const int idx = tid + it * 256;
            const int f = idx & 63, r = idx >> 6;
            const int ga = ((b0 + r) * Tt + t) * 64 + f;
            const float xv = values[ga], mv = masks[ga], dv = deltas[ga];
            s->xT[f * 8 + r] = xv;
            s->actT[(64 + f) * 8 + r] = mv;
            s->dT[f * 8 + r] = dv;
            s->gxT[f * 8 + r] = __expf(-fmaxf(dv * s->wdxv[f] + s->b_dxv[f], 0.f));
        }
        __syncthreads();

        // ---- Stage B: gamma_h + decay h (duplicated, all 128 units) ------
        {
            float a0 = 0.f, a1 = 0.f, a2 = 0.f, a3 = 0.f;
#pragma unroll 8
            for (int k = 0; k < 64; ++k) {
                const float w = s->WdhT[k * 128 + hu];
                const float4 d4 = *reinterpret_cast<const float4*>(&s->dT[k * 8 + 4 * hg]);
                a0 += w * d4.x; a1 += w * d4.y; a2 += w * d4.z; a3 += w * d4.w;
            }
            const float bb = s->b_dhv[hu];
            const int rb = 4 * hg;
            s->actT[(128 + hu) * 8 + rb]     = s->hT[hu * 8 + rb]     * __expf(-fmaxf(a0 + bb, 0.f));
            s->actT[(128 + hu) * 8 + rb + 1] = s->hT[hu * 8 + rb + 1] * __expf(-fmaxf(a1 + bb, 0.f));
            s->actT[(128 + hu) * 8 + rb + 2] = s->hT[hu * 8 + rb + 2] * __expf(-fmaxf(a2 + bb, 0.f));
            s->actT[(128 + hu) * 8 + rb + 3] = s->hT[hu * 8 + rb + 3] * __expf(-fmaxf(a3 + bb, 0.f));
        }
        __syncthreads();

        // ---- Stage C: x_h for my f-slice (tid<128) -----------------------
        float x_h = 0.f, xv = 0.f, mv = 0.f, l1 = 0.f;
        if (tid < 128) {
            float c0 = 0.f, c1 = 0.f;
#pragma unroll 8
            for (int k = 0; k < 128; k += 2) {
                c0 += s->Whrsl[k * 16 + lf]       * s->actT[(128 + k) * 8 + cr];
                c1 += s->Whrsl[(k + 1) * 16 + lf] * s->actT[(129 + k) * 8 + cr];
            }
            x_h = c0 + c1 + s->b_hrv[lf];
            xv = s->xT[fg * 8 + cr];
            mv = s->actT[(64 + fg) * 8 + cr];
            l1 = fabsf(xv - x_h) * mv;
            const float x_c = mv * xv + (1.f - mv) * x_h;
            float* dst = &s->xcT[fg * 8 + cr];
            *dst = x_c;
            push3(dst, rank, x_c);
        }
        CSYNC();

        // ---- Stage D: z_h, alpha, c_h, c_c, losses (tid<128) -------------
        if (tid < 128) {
            float z = 0.f;
#pragma unroll 8
            for (int k = 0; k < 64; ++k)
                z += s->Wfrsl[k * 16 + lf] * s->xcT[k * 8 + cr];
            z += s->b_frv[lf];
            float al = 0.f;
#pragma unroll 8
            for (int k = 0; k < 64; ++k)
                al += s->Wwcsl[k * 16 + lf] * s->gxT[k * 8 + cr];
#pragma unroll 8
            for (int k = 0; k < 64; ++k)
                al += s->Wwcsl[(64 + k) * 16 + lf] * s->actT[(64 + k) * 8 + cr];
            al += s->b_wcv[lf];
            const float c_h = al * z + (1.f - al) * x_h;
            lacc += (l1 + fabsf(xv - z) * mv + fabsf(xv - c_h) * mv) * s->inv_msum[t];
            const float c_c = mv * xv + (1.f - mv) * c_h;
            out[1 + Bsz + ((b0 + cr) * Tt + t) * 64 + fg] = c_c;   // imputations
            float* dst = &s->actT[fg * 8 + cr];
            *dst = c_c;
            push3(dst, rank, c_c);
        }
        CSYNC();

        // ---- Stage E: gates GEMM slice (k-half ko, out lo, all 8 rows) ---
        {
            unsigned long long accA = 0ull, accB = 0ull;
            const float* wgp = s->Wg + (ko << 7) * 128 + lo;
            const float* ap = s->actT + (ko << 7) * 8;
#pragma unroll 8
            for (int k = 0; k < 128; ++k) {
                const float w = wgp[k * 128];
                const ulonglong2 av = *reinterpret_cast<const ulonglong2*>(&ap[k * 8]);
                const unsigned long long w2 = splat2(w);
                accA = fma2(w2, av.x, accA);
                accB = fma2(w2, av.y, accB);
            }
            unsigned long long accC = 0ull, accD = 0ull;
#pragma unroll 8
            for (int k = 0; k < 128; ++k) {
                const float w = wgp[k * 128];
                const ulonglong2 av = *reinterpret_cast<const ulonglong2*>(&ap[k * 8 + 4]);
                const unsigned long long w2 = splat2(w);
                accC = fma2(w2, av.x, accC);
                accD = fma2(w2, av.y, accD);
            }
            F2U uA, uB, uC, uD; uA.u = accA; uB.u = accB; uC.u = accC; uD.u = accD;
            float* gdst = ko ? s->gTb : s->gTa;
            gdst[0 * 128 + lo] = uA.f.x; gdst[1 * 128 + lo] = uA.f.y;
            gdst[2 * 128 + lo] = uB.f.x; gdst[3 * 128 + lo] = uB.f.y;
            gdst[4 * 128 + lo] = uC.f.x; gdst[5 * 128 + lo] = uC.f.y;
            gdst[6 * 128 + lo] = uD.f.x; gdst[7 * 128 + lo] = uD.f.y;
        }
        __syncthreads();

        // ---- Stage F: LSTM update on my 32 units, push h -----------------
        {
            const float ig = s->gTa[frow * 128 + ful]      + s->gTb[frow * 128 + ful]      + s->bg[ful];
            const float fgt= s->gTa[frow * 128 + 32 + ful] + s->gTb[frow * 128 + 32 + ful] + s->bg[32 + ful];
            const float gg = s->gTa[frow * 128 + 64 + ful] + s->gTb[frow * 128 + 64 + ful] + s->bg[64 + ful];
            const float og = s->gTa[frow * 128 + 96 + ful] + s->gTb[frow * 128 + 96 + ful] + s->bg[96 + ful];
            const float cn = sigm(fgt) * s->cT[ful * 8 + frow] + sigm(ig) * tanh_e(gg);
            s->cT[ful * 8 + frow] = cn;
            const float hn = sigm(og) * tanh_e(cn);
            const int gu = 32 * (int)rank + ful;
            float* dst = &s->hT[gu * 8 + frow];
            *dst = hn;
            push3(dst, rank, hn);
        }
        CSYNC();
    }

    // ---- epilogue: x_loss block reduce + atomic ---------------------------
    s->red[tid] = lacc; __syncthreads();
    for (int off = 128; off > 0; off >>= 1) {
        if (tid < off) s->red[tid] += s->red[tid + off];
        __syncthreads();
    }
    if (tid == 0) atomicAdd(&g_xloss, s->red[0]);

    // ---- epilogue: y head (rank 0, warp w -> row w) -----------------------
    if (rank == 0) {
        const int wid = tid >> 5, lid = tid & 31;
        float acc = 0.f;
#pragma unroll
        for (int u = lid; u < Hh; u += 32)
            acc += s->hT[u * 8 + wid] * W_out[u];
#pragma unroll
        for (int off = 16; off > 0; off >>= 1)
            acc += __shfl_down_sync(0xffffffffu, acc, off);
        if (lid == 0) {
            const int b = b0 + wid;
            const float yh = acc + b_out[0];
            out[1 + b] = 1.f / (1.f + expf(-yh));
            const float lab = labels[b];
            const float mx = fmaxf(-yh, 0.f);
            const float yl = yh - yh * lab + mx + logf(expf(-mx) + expf(-yh - mx));
            atomicAdd(&g_yloss, yl * is_train[b]);
        }
    }
}

// ---------------- finalize --------------------------------------------------
__global__ void finalize_loss(float* __restrict__ out) {
    out[0] = g_xloss * (1.f / (float)Tt) + 0.3f * (g_yloss / (g_istrain + 1e-5f));
}

// ---------------- launch ----------------------------------------------------
extern "C" void kernel_launch(void* const* d_in, const int* in_sizes, int n_in,
                              void* d_out, int out_size) {
    (void)in_sizes; (void)n_in; (void)out_size;
    const float* values   = (const float*)d_in[0];
    const float* masks    = (const float*)d_in[1];
    const float* deltas   = (const float*)d_in[2];
    const float* labels   = (const float*)d_in[3];
    const float* is_train = (const float*)d_in[4];
    const float* W_dh = (const float*)d_in[5];
    const float* b_dh = (const float*)d_in[6];
    const float* W_dx = (const float*)d_in[7];
    const float* b_dx = (const float*)d_in[8];
    const float* W_hr = (const float*)d_in[9];
    const float* b_hr = (const float*)d_in[10];
    const float* W_fr = (const float*)d_in[11];
    const float* b_fr = (const float*)d_in[12];
    const float* W_wc = (const float*)d_in[13];
    const float* b_wc = (const float*)d_in[14];
    const float* W_ih = (const float*)d_in[15];
    const float* b_ih = (const float*)d_in[16];
    const float* W_hh = (const float*)d_in[17];
    const float* b_hh = (const float*)d_in[18];
    const float* W_out = (const float*)d_in[19];
    const float* b_out = (const float*)d_in[20];
    float* out = (float*)d_out;

    static const size_t smem_bytes = sizeof(SmemMain);
    cudaFuncSetAttribute(brits_main, cudaFuncAttributeMaxDynamicSharedMemorySize,
                         (int)smem_bytes);

    prep_all<<<Tt + 1 + 128, 256>>>(masks, is_train, W_dh, W_dx, W_hr, W_fr, W_wc,
                                    W_ih, b_ih, W_hh, b_hh);
    brits_main<<<NCTA, 256, smem_bytes>>>(values, masks, deltas, labels, is_train,
                                          b_dh, b_dx, b_hr, b_fr, b_wc, W_out, b_out, out);
    finalize_loss<<<1, 1>>>(out);
}

// round 9
// speedup vs baseline: 2.6682x; 1.3129x over previous
#include <cuda_runtime.h>
#include <cuda_bf16.h>
#include <math.h>

// BRITS-style recurrent imputation. B=256, T=512, F=64, H=128, gates=512.
// 32 clusters x 4 CTAs = 128 CTAs. Cluster owns 8 batch rows. CTA rank c owns
// gate outputs for h-units [32c,32c+32) (weights resident in smem, 128KB) and
// the f-slice [16c,16c+16) of the C/D matvecs. All cluster barriers are split
// arrive/wait with independent work hiding the exchange latency.
// Output: [loss(1), predictions(256), imputations(256*512*64)].

#define Bsz 256
#define Tt  512
#define Ff  64
#define Hh  128
#define CROWS 8
#define NCLUST 32
#define NCTA (NCLUST * 4)

// ---------------- device-global staging (static, allocation-free) ----------
__device__ __align__(16) float g_Wg[4 * 256 * 128];   // [rank][k][lo]
__device__ float g_bgsl[4 * 128];
__device__ float g_WdhT[64 * 128];                    // [k][hu]
__device__ float g_Whrsl[4 * 128 * 16];               // [rank][k][lf]
__device__ float g_Wfrsl[4 * 64 * 16];                // [rank][k][lf], diag zeroed
__device__ float g_Wwcsl[4 * 128 * 16];               // [rank][k][lf]
__device__ float g_wdx[64];
__device__ float g_inv_msum[Tt];
__device__ float g_istrain;
__device__ float g_xloss;
__device__ float g_yloss;

// ---------------- helpers --------------------------------------------------
__device__ __forceinline__ unsigned long long splat2(float w) {
    unsigned long long r; unsigned int wi = __float_as_uint(w);
    asm("mov.b64 %0, {%1, %2};" : "=l"(r) : "r"(wi), "r"(wi));
    return r;
}
__device__ __forceinline__ unsigned long long fma2(unsigned long long a,
                                                   unsigned long long b,
                                                   unsigned long long c) {
    unsigned long long d;
    asm("fma.rn.f32x2 %0, %1, %2, %3;" : "=l"(d) : "l"(a), "l"(b), "l"(c));
    return d;
}
union F2U { unsigned long long u; float2 f; };

__device__ __forceinline__ float sigm(float x) { return 1.f / (1.f + __expf(-x)); }
__device__ __forceinline__ float tanh_e(float x) { return 1.f - 2.f / (__expf(2.f * x) + 1.f); }

__device__ __forceinline__ void st_peer_f32(const void* smem_ptr, unsigned int peer, float v) {
    unsigned int la = (unsigned int)__cvta_generic_to_shared(smem_ptr);
    unsigned int ra;
    asm volatile("mapa.shared::cluster.u32 %0, %1, %2;" : "=r"(ra) : "r"(la), "r"(peer));
    asm volatile("st.shared::cluster.f32 [%0], %1;" :: "r"(ra), "f"(v));
}
__device__ __forceinline__ void push3(const void* p, unsigned int rank, float v) {
#pragma unroll
    for (int d = 1; d < 4; ++d) st_peer_f32(p, (rank + d) & 3u, v);
}
#define CARRIVE() asm volatile("barrier.cluster.arrive.aligned;" ::: "memory")
#define CWAIT()   asm volatile("barrier.cluster.wait.aligned;" ::: "memory")

// ---------------- prep -----------------------------------------------------
__global__ void prep_all(const float* __restrict__ masks, const float* __restrict__ is_train,
                         const float* __restrict__ W_dh, const float* __restrict__ W_dx,
                         const float* __restrict__ W_hr, const float* __restrict__ W_fr,
                         const float* __restrict__ W_wc,
                         const float* __restrict__ W_ih, const float* __restrict__ b_ih,
                         const float* __restrict__ W_hh, const float* __restrict__ b_hh) {
    __shared__ float red[256];
    const int bx = blockIdx.x;
    if (bx < Tt) {
        float s = 0.f;
        for (int i = threadIdx.x; i < Bsz * Ff; i += 256) {
            int b = i / Ff, f = i % Ff;
            s += masks[(b * Tt + bx) * Ff + f];
        }
        red[threadIdx.x] = s; __syncthreads();
        for (int off = 128; off > 0; off >>= 1) {
            if (threadIdx.x < off) red[threadIdx.x] += red[threadIdx.x + off];
            __syncthreads();
        }
        if (threadIdx.x == 0) g_inv_msum[bx] = 1.f / (red[0] + 1e-5f);
        return;
    }
    if (bx == Tt) {
        red[threadIdx.x] = is_train[threadIdx.x]; __syncthreads();
        for (int off = 128; off > 0; off >>= 1) {
            if (threadIdx.x < off) red[threadIdx.x] += red[threadIdx.x + off];
            __syncthreads();
        }
        if (threadIdx.x == 0) { g_istrain = red[0]; g_xloss = 0.f; g_yloss = 0.f; }
        return;
    }
    const int idx = (bx - Tt - 1) * 256 + threadIdx.x;
    const int stride = 128 * 256;
    for (int i = idx; i < 4 * 256 * 128; i += stride) {
        int c = i >> 15, k = (i >> 7) & 255, lo = i & 127;
        int gate = lo >> 5, ul = lo & 31;
        int go = gate * 128 + c * 32 + ul;
        g_Wg[i] = (k < 128) ? W_ih[go * 128 + k] : W_hh[go * 128 + (k - 128)];
    }
    for (int i = idx; i < 4 * 128; i += stride) {
        int c = i >> 7, lo = i & 127;
        int gate = lo >> 5, ul = lo & 31;
        int go = gate * 128 + c * 32 + ul;
        g_bgsl[i] = b_ih[go] + b_hh[go];
    }
    for (int i = idx; i < 64 * 128; i += stride) { int k = i >> 7, hu = i & 127; g_WdhT[i] = W_dh[hu * 64 + k]; }
    for (int i = idx; i < 4 * 128 * 16; i += stride) {
        int c = i >> 11, k = (i >> 4) & 127, lf = i & 15;
        g_Whrsl[i] = W_hr[(16 * c + lf) * 128 + k];
    }
    for (int i = idx; i < 4 * 64 * 16; i += stride) {
        int c = i >> 10, k = (i >> 4) & 63, lf = i & 15;
        int fg = 16 * c + lf;
        g_Wfrsl[i] = (k == fg) ? 0.f : W_fr[fg * 64 + k];
    }
    for (int i = idx; i < 4 * 128 * 16; i += stride) {
        int c = i >> 11, k = (i >> 4) & 127, lf = i & 15;
        g_Wwcsl[i] = W_wc[(16 * c + lf) * 128 + k];
    }
    for (int i = idx; i < 64; i += stride) g_wdx[i] = W_dx[i * 64 + i];
}

// ---------------- smem layout ----------------------------------------------
struct __align__(16) SmemMain {
    float Wg[256 * 128];      // 128KB [k][lo]
    float WdhT[64 * 128];     // 32KB  [k][hu]
    float Whrsl[128 * 16];    // 8KB
    float Wfrsl[64 * 16];     // 4KB
    float Wwcsl[128 * 16];    // 8KB
    float actT[256 * 8];      // [k][row]: 0-63 c_c, 64-127 m, 128-255 decayed h
    float hT[128 * 8];        // raw h (replicated via DSMEM)
    float cT[32 * 8];
    float dT[64 * 8];
    float gxT[64 * 8];
    float xcT[64 * 8];
    float xT[64 * 8];
    float gTp[4 * 8 * 128];   // gate partials, u64 view [kq][rowpair][out]  16KB
    float Cpart[2 * 128];
    float Apart[2 * 128];
    float inv_msum[Tt];
    float bg[128];
    float b_dhv[128];
    float b_hrv[16]; float b_frv[16]; float b_wcv[16];
    float wdxv[64]; float b_dxv[64];
    float red[256];
};

__device__ __forceinline__ void e_loop(unsigned long long* acc,
                                       const float* __restrict__ wq,
                                       const float* __restrict__ aq) {
#pragma unroll 8
    for (int k = 0; k < 64; ++k) {
        const float2 wv = *reinterpret_cast<const float2*>(wq + k * 128);
        const unsigned long long w0 = splat2(wv.x);
        const unsigned long long w1 = splat2(wv.y);
        const ulonglong2 a01 = *reinterpret_cast<const ulonglong2*>(aq + k * 8);
        const ulonglong2 a23 = *reinterpret_cast<const ulonglong2*>(aq + k * 8 + 4);
        acc[0] = fma2(w0, a01.x, acc[0]); acc[1] = fma2(w0, a01.y, acc[1]);
        acc[2] = fma2(w0, a23.x, acc[2]); acc[3] = fma2(w0, a23.y, acc[3]);
        acc[4] = fma2(w1, a01.x, acc[4]); acc[5] = fma2(w1, a01.y, acc[5]);
        acc[6] = fma2(w1, a23.x, acc[6]); acc[7] = fma2(w1, a23.y, acc[7]);
    }
}

// ---------------- main persistent scan kernel ------------------------------
__global__ __launch_bounds__(256, 1) __cluster_dims__(4, 1, 1)
void brits_main(const float* __restrict__ values, const float* __restrict__ masks,
                const float* __restrict__ deltas, const float* __restrict__ labels,
                const float* __restrict__ is_train,
                const float* __restrict__ b_dh, const float* __restrict__ b_dx,
                const float* __restrict__ b_hr, const float* __restrict__ b_fr,
                const float* __restrict__ b_wc,
                const float* __restrict__ W_out, const float* __restrict__ b_out,
                float* __restrict__ out) {
    extern __shared__ char smem_raw[];
    SmemMain* s = reinterpret_cast<SmemMain*>(smem_raw);

    unsigned int rank;
    asm("mov.u32 %0, %%cluster_ctarank;" : "=r"(rank));

    const int tid = threadIdx.x;
    const int b0 = (blockIdx.x >> 2) * CROWS;

    // ---- init smem ----
    for (int i = tid; i < 256 * 128; i += 256) s->Wg[i] = g_Wg[(rank << 15) + i];
    for (int i = tid; i < 64 * 128; i += 256) s->WdhT[i] = g_WdhT[i];
    for (int i = tid; i < 128 * 16; i += 256) s->Whrsl[i] = g_Whrsl[(rank << 11) + i];
    for (int i = tid; i < 64 * 16; i += 256) s->Wfrsl[i] = g_Wfrsl[(rank << 10) + i];
    for (int i = tid; i < 128 * 16; i += 256) s->Wwcsl[i] = g_Wwcsl[(rank << 11) + i];
    for (int i = tid; i < Tt; i += 256) s->inv_msum[i] = g_inv_msum[i];
    for (int i = tid; i < 128 * 8; i += 256) s->hT[i] = 0.f;
    if (tid < 128) { s->bg[tid] = g_bgsl[(rank << 7) + tid]; s->b_dhv[tid] = b_dh[tid]; }
    if (tid < 16) {
        s->b_hrv[tid] = b_hr[16 * rank + tid];
        s->b_frv[tid] = b_fr[16 * rank + tid];
        s->b_wcv[tid] = b_wc[16 * rank + tid];
    }
    if (tid < 64) { s->wdxv[tid] = g_wdx[tid]; s->b_dxv[tid] = b_dx[tid]; }
    s->cT[tid] = 0.f;  // 256 == 32*8
    float lacc = 0.f;
    __syncthreads();
    CARRIVE();                     // pre-loop arrive for first h-wait

    // mappings
    const int lf = tid & 15, cr8 = (tid >> 4) & 7, kh = tid >> 7;  // C/D partials
    const int fg = 16 * (int)rank + lf;
    const int o2 = tid & 63, kq = tid >> 6;                        // E
    const int ful = tid & 31, frow = tid >> 5;                     // F
    const int hu = tid & 127, hg = tid >> 7;                       // B

    // prefetch t=0 inputs
    float px[2], pm[2], pd[2];
#pragma unroll
    for (int it = 0; it < 2; ++it) {
        const int idx = tid + (it << 8);
        const int f = idx & 63, r = idx >> 6;
        const int ga = ((b0 + r) * Tt) * 64 + f;
        px[it] = values[ga]; pm[it] = masks[ga]; pd[it] = deltas[ga];
    }

    for (int t = 0; t < Tt; ++t) {
        // ---- Stage A: publish prefetched inputs + gamma_x ----------------
#pragma unroll
        for (int it = 0; it < 2; ++it) {
            const int idx = tid + (it << 8);
            const int f = idx & 63, r = idx >> 6;
            s->xT[f * 8 + r] = px[it];
            s->actT[(64 + f) * 8 + r] = pm[it];
            s->dT[f * 8 + r] = pd[it];
            s->gxT[f * 8 + r] = __expf(-fmaxf(pd[it] * s->wdxv[f] + s->b_dxv[f], 0.f));
        }
        __syncthreads();
        CWAIT();                                   // h exchange complete

        // ---- Stage B: gamma_h + decay h (all 128 units, 4 rows/thread) ---
        {
            float a0 = 0.f, a1 = 0.f, a2 = 0.f, a3 = 0.f;
#pragma unroll 8
            for (int k = 0; k < 64; ++k) {
                const float w = s->WdhT[k * 128 + hu];
                const float4 d4 = *reinterpret_cast<const float4*>(&s->dT[k * 8 + 4 * hg]);
                a0 += w * d4.x; a1 += w * d4.y; a2 += w * d4.z; a3 += w * d4.w;
            }
            const float bb = s->b_dhv[hu];
            const int rb = 4 * hg;
            s->actT[(128 + hu) * 8 + rb]     = s->hT[hu * 8 + rb]     * __expf(-fmaxf(a0 + bb, 0.f));
            s->actT[(128 + hu) * 8 + rb + 1] = s->hT[hu * 8 + rb + 1] * __expf(-fmaxf(a1 + bb, 0.f));
            s->actT[(128 + hu) * 8 + rb + 2] = s->hT[hu * 8 + rb + 2] * __expf(-fmaxf(a2 + bb, 0.f));
            s->actT[(128 + hu) * 8 + rb + 3] = s->hT[hu * 8 + rb + 3] * __expf(-fmaxf(a3 + bb, 0.f));
        }
        __syncthreads();

        // prefetch t+1 inputs (consumed next A; latency hidden under C/D/E)
        {
            const int tn = (t + 1 < Tt) ? t + 1 : t;
#pragma unroll
            for (int it = 0; it < 2; ++it) {
                const int idx = tid + (it << 8);
                const int f = idx & 63, r = idx >> 6;
                const int ga = ((b0 + r) * Tt + tn) * 64 + f;
                px[it] = values[ga]; pm[it] = masks[ga]; pd[it] = deltas[ga];
            }
        }

        // ---- Stage C: x_h partials (all 256 threads, k-split) ------------
        {
            float cp = 0.f;
            const float* wc = s->Whrsl + (kh << 6) * 16 + lf;
            const float* ac = s->actT + (128 + (kh << 6)) * 8 + cr8;
#pragma unroll 8
            for (int k = 0; k < 64; ++k)
                cp += wc[k * 16] * ac[k * 8];
            s->Cpart[(kh << 7) + (cr8 << 4) + lf] = cp;
        }
        __syncthreads();

        // ---- C combine: x_h, x_c, push (tid<128) -------------------------
        float x_h = 0.f, xv = 0.f, mv = 0.f, l1 = 0.f;
        if (tid < 128) {
            x_h = s->Cpart[(cr8 << 4) + lf] + s->Cpart[128 + (cr8 << 4) + lf] + s->b_hrv[lf];
            xv = s->xT[fg * 8 + cr8];
            mv = s->actT[(64 + fg) * 8 + cr8];
            l1 = fabsf(xv - x_h) * mv;
            const float x_c = mv * xv + (1.f - mv) * x_h;
            float* dst = &s->xcT[fg * 8 + cr8];
            *dst = x_c;
            push3(dst, rank, x_c);
        }
        CARRIVE();                                 // x_c pushed

        // ---- alpha partials (no x_c dependency; hides x_c exchange) ------
        {
            float ap = 0.f;
            const float* wa = s->Wwcsl + (kh << 6) * 16 + lf;
            const float* aa = kh ? (s->actT + 64 * 8 + cr8) : (s->gxT + cr8);
#pragma unroll 8
            for (int k = 0; k < 64; ++k)
                ap += wa[k * 16] * aa[k * 8];
            s->Apart[(kh << 7) + (cr8 << 4) + lf] = ap;
        }
        __syncthreads();
        CWAIT();                                   // x_c exchange complete

        // ---- Stage D: z_h, alpha, c_h, c_c, losses (tid<128) -------------
        if (tid < 128) {
            float z = 0.f;
#pragma unroll 8
            for (int k = 0; k < 64; ++k)
                z += s->Wfrsl[k * 16 + lf] * s->xcT[k * 8 + cr8];
            z += s->b_frv[lf];
            const float al = s->Apart[(cr8 << 4) + lf] + s->Apart[128 + (cr8 << 4) + lf] + s->b_wcv[lf];
            const float c_h = al * z + (1.f - al) * x_h;
            lacc += (l1 + fabsf(xv - z) * mv + fabsf(xv - c_h) * mv) * s->inv_msum[t];
            const float c_c = mv * xv + (1.f - mv) * c_h;
            out[1 + Bsz + ((b0 + cr8) * Tt + t) * 64 + fg] = c_c;
            float* dst = &s->actT[fg * 8 + cr8];
            *dst = c_c;
            push3(dst, rank, c_c);
        }
        __syncthreads();                           // local c_c visible intra-CTA
        CARRIVE();                                 // c_c pushed

        // ---- Stage E: gates GEMM (2 outs x k-quarter per thread) ---------
        {
            unsigned long long acc[8] = {0ull,0ull,0ull,0ull,0ull,0ull,0ull,0ull};
            const float* wq = s->Wg + (kq << 6) * 128 + (o2 << 1);
            const float* aq = s->actT + (kq << 6) * 8;
            if (kq != 0) e_loop(acc, wq, aq);      // k>=64: m + h, no c_c dep
            CWAIT();                               // c_c exchange complete
            if (kq == 0) e_loop(acc, wq, aq);      // k<64: c_c
            unsigned long long* gp = reinterpret_cast<unsigned long long*>(s->gTp);
#pragma unroll
            for (int rp = 0; rp < 4; ++rp) {
                ulonglong2 v; v.x = acc[rp]; v.y = acc[4 + rp];
                *reinterpret_cast<ulonglong2*>(&gp[(kq << 9) + (rp << 7) + (o2 << 1)]) = v;
            }
        }
        __syncthreads();

        // ---- Stage F: LSTM update on my 32 units, push h -----------------
        {
            const int rp = frow >> 1, sel = frow & 1;
            float gv[4];
#pragma unroll
            for (int g = 0; g < 4; ++g) {
                const int o = g * 32 + ful;
                float v = s->bg[o];
#pragma unroll
                for (int q = 0; q < 4; ++q)
                    v += s->gTp[(q << 10) + (rp << 8) + (o << 1) + sel];
                gv[g] = v;
            }
            const float cn = sigm(gv[1]) * s->cT[ful * 8 + frow] + sigm(gv[0]) * tanh_e(gv[2]);
            s->cT[ful * 8 + frow] = cn;
            const float hn = sigm(gv[3]) * tanh_e(cn);
            const int gu = 32 * (int)rank + ful;
            float* dst = &s->hT[gu * 8 + frow];
            *dst = hn;
            push3(dst, rank, hn);
        }
        CARRIVE();                                 // h pushed
    }

    CWAIT();                                       // final h exchange

    // ---- epilogue: x_loss block reduce + atomic ---------------------------
    s->red[tid] = lacc; __syncthreads();
    for (int off = 128; off > 0; off >>= 1) {
        if (tid < off) s->red[tid] += s->red[tid + off];
        __syncthreads();
    }
    if (tid == 0) atomicAdd(&g_xloss, s->red[0]);

    // ---- epilogue: y head (rank 0, warp w -> row w) -----------------------
    if (rank == 0) {
        const int wid = tid >> 5, lid = tid & 31;
        float acc = 0.f;
#pragma unroll
        for (int u = lid; u < Hh; u += 32)
            acc += s->hT[u * 8 + wid] * W_out[u];
#pragma unroll
        for (int off = 16; off > 0; off >>= 1)
            acc += __shfl_down_sync(0xffffffffu, acc, off);
        if (lid == 0) {
            const int b = b0 + wid;
            const float yh = acc + b_out[0];
            out[1 + b] = 1.f / (1.f + expf(-yh));
            const float lab = labels[b];
            const float mx = fmaxf(-yh, 0.f);
            const float yl = yh - yh * lab + mx + logf(expf(-mx) + expf(-yh - mx));
            atomicAdd(&g_yloss, yl * is_train[b]);
        }
    }
}

// ---------------- finalize --------------------------------------------------
__global__ void finalize_loss(float* __restrict__ out) {
    out[0] = g_xloss * (1.f / (float)Tt) + 0.3f * (g_yloss / (g_istrain + 1e-5f));
}

// ---------------- launch ----------------------------------------------------
extern "C" void kernel_launch(void* const* d_in, const int* in_sizes, int n_in,
                              void* d_out, int out_size) {
    (void)in_sizes; (void)n_in; (void)out_size;
    const float* values   = (const float*)d_in[0];
    const float* masks    = (const float*)d_in[1];
    const float* deltas   = (const float*)d_in[2];
    const float* labels   = (const float*)d_in[3];
    const float* is_train = (const float*)d_in[4];
    const float* W_dh = (const float*)d_in[5];
    const float* b_dh = (const float*)d_in[6];
    const float* W_dx = (const float*)d_in[7];
    const float* b_dx = (const float*)d_in[8];
    const float* W_hr = (const float*)d_in[9];
    const float* b_hr = (const float*)d_in[10];
    const float* W_fr = (const float*)d_in[11];
    const float* b_fr = (const float*)d_in[12];
    const float* W_wc = (const float*)d_in[13];
    const float* b_wc = (const float*)d_in[14];
    const float* W_ih = (const float*)d_in[15];
    const float* b_ih = (const float*)d_in[16];
    const float* W_hh = (const float*)d_in[17];
    const float* b_hh = (const float*)d_in[18];
    const float* W_out = (const float*)d_in[19];
    const float* b_out = (const float*)d_in[20];
    float* out = (float*)d_out;

    static const size_t smem_bytes = sizeof(SmemMain);
    cudaFuncSetAttribute(brits_main, cudaFuncAttributeMaxDynamicSharedMemorySize,
                         (int)smem_bytes);

    prep_all<<<Tt + 1 + 128, 256>>>(masks, is_train, W_dh, W_dx, W_hr, W_fr, W_wc,
                                    W_ih, b_ih, W_hh, b_hh);
    brits_main<<<NCTA, 256, smem_bytes>>>(values, masks, deltas, labels, is_train,
                                          b_dh, b_dx, b_hr, b_fr, b_wc, W_out, b_out, out);
    finalize_loss<<<1, 1>>>(out);
}